// round 12
// baseline (speedup 1.0000x reference)
#include <cuda_runtime.h>
#include <cuda_fp16.h>
#include <math.h>
#include <stdint.h>

#define Bb   4
#define Lseq 2048
#define Dm   1024
#define Hh   4
#define DHd  256
#define CHK  32
#define NCk  (Lseq/CHK)      // 64
#define Mrows (Bb*Lseq)      // 8192
#define MD (Mrows*Dm)

// ---------------- scratch ----------------
__device__ float g_qlin[MD], g_klin[MD], g_vlin[MD];
__device__ float g_u[MD];
__device__ float g_A2[Bb*Hh*NCk*CHK*CHK];
__device__ float g_beta[Mrows*Hh], g_gamma[Mrows*Hh], g_mixlin[Mrows*Hh], g_mix[Mrows*Hh];
__device__ float g_od[MD], g_ema[MD];
__device__ float g_pg[Mrows*Hh];
__device__ float g_sst[Bb*Hh*NCk*DHd];
__device__ __half g_x16[MD];
__device__ __half g_oc16[MD];
__device__ __half g_wt16[4*Dm*Dm];
__device__ __half g_wq16[Bb*Hh*NCk*64*256];
__device__ __half g_kt16[Bb*Hh*NCk*256*32];

__device__ __forceinline__ float sigm(float x){ return 1.0f/(1.0f+__expf(-x)); }

__device__ __forceinline__ uint32_t smem_u32(const void* p){
    uint32_t a;
    asm("{ .reg .u64 t; cvta.to.shared.u64 t, %1; cvt.u32.u64 %0, t; }" : "=r"(a) : "l"(p));
    return a;
}
__device__ __forceinline__ uint32_t sw128(uint32_t b){ return b ^ ((b >> 3) & 0x70); }

__device__ __forceinline__ void cpa16(uint32_t dst, const void* src){
    asm volatile("cp.async.cg.shared.global [%0], [%1], 16;" :: "r"(dst), "l"(src) : "memory");
}
#define CP_COMMIT() asm volatile("cp.async.commit_group;" ::: "memory")
#define CP_WAIT(n)  asm volatile("cp.async.wait_group %0;" :: "n"(n) : "memory")

#define LDSM_X4(r0,r1,r2,r3, addr) \
    asm volatile("ldmatrix.sync.aligned.m8n8.x4.shared.b16 {%0,%1,%2,%3}, [%4];" \
        : "=r"(r0),"=r"(r1),"=r"(r2),"=r"(r3) : "r"(addr))
#define LDSM_X4T(r0,r1,r2,r3, addr) \
    asm volatile("ldmatrix.sync.aligned.m8n8.x4.trans.shared.b16 {%0,%1,%2,%3}, [%4];" \
        : "=r"(r0),"=r"(r1),"=r"(r2),"=r"(r3) : "r"(addr))

#define MMAF16(d, a, b) \
    asm volatile("mma.sync.aligned.m16n8k16.row.col.f32.f16.f16.f32 " \
        "{%0,%1,%2,%3}, {%4,%5,%6,%7}, {%8,%9}, {%0,%1,%2,%3};" \
        : "+f"((d)[0]),"+f"((d)[1]),"+f"((d)[2]),"+f"((d)[3]) \
        : "r"((a)[0]),"r"((a)[1]),"r"((a)[2]),"r"((a)[3]), "r"((b)[0]),"r"((b)[1]))

__device__ __forceinline__ uint32_t f2h2(float a, float b){
    __half2 h = __floats2half2_rn(a, b);
    return *(uint32_t*)&h;
}
__device__ __forceinline__ void split2h(float a, float b, uint32_t &hi, uint32_t &lo){
    __half ah = __float2half(a), bh = __float2half(b);
    __half al = __float2half(a - __half2float(ah));
    __half bl = __float2half(b - __half2float(bh));
    hi = ((uint32_t)*(uint16_t*)&bh << 16) | *(uint16_t*)&ah;
    lo = ((uint32_t)*(uint16_t*)&bl << 16) | *(uint16_t*)&al;
}

// ================= fp16 HMMA GEMM: 128x128 tile, BK=64, 3 stages, single-sync ===
#define TILE16 16384
#define STAGEF (2*TILE16)

__global__ __launch_bounds__(256,2) void mma_gemm_kernel(
    const __half* __restrict__ A,
    const __half* __restrict__ BtBase,
    int woff, float* __restrict__ C0, float* __restrict__ C1, float* __restrict__ C2)
{
    extern __shared__ char dyn[];
    uint32_t raw = smem_u32(dyn);
    uint32_t base = (raw + 127u) & ~127u;

    int z = blockIdx.z;
    const __half* Bt = BtBase + (size_t)(woff + z) * Dm * Dm;
    float* C = (z == 0) ? C0 : ((z == 1) ? C1 : C2);

    int tid = threadIdx.x, lane = tid & 31, wid = tid >> 5;
    int wm = wid >> 1, wn = wid & 1;
    int m0 = blockIdx.y * 128, n0 = blockIdx.x * 128;

    const __half* gA = A  + (size_t)m0 * Dm;
    const __half* gB = Bt + (size_t)n0 * Dm;

    float acc[2][8][4];
#pragma unroll
    for (int f=0; f<2; f++)
#pragma unroll
        for (int j=0; j<8; j++)
#pragma unroll
            for (int e=0; e<4; e++) acc[f][j][e] = 0.0f;

    const int NSTEP = Dm / 64;   // 16

#pragma unroll
    for (int ps=0; ps<2; ps++){
        uint32_t sb = base + ps*STAGEF;
        int k0 = ps*64;
#pragma unroll
        for (int t=0;t<4;t++){
            int c = tid + t*256;
            int row = c >> 3, col = c & 7;
            size_t go = (size_t)row*Dm + k0 + col*8;
            uint32_t so = sw128((uint32_t)(row*128 + col*16));
            cpa16(sb + so,          gA + go);
            cpa16(sb + TILE16 + so, gB + go);
        }
        CP_COMMIT();
    }

    for (int s = 0; s < NSTEP; s++){
        if (s == NSTEP-1) { CP_WAIT(0); } else { CP_WAIT(1); }
        __syncthreads();

        if (s+2 < NSTEP){
            uint32_t nb = base + ((s+2) % 3)*STAGEF;
            int k0 = (s+2)*64;
#pragma unroll
            for (int t=0;t<4;t++){
                int c = tid + t*256;
                int row = c >> 3, col = c & 7;
                size_t go = (size_t)row*Dm + k0 + col*8;
                uint32_t so = sw128((uint32_t)(row*128 + col*16));
                cpa16(nb + so,          gA + go);
                cpa16(nb + TILE16 + so, gB + go);
            }
            CP_COMMIT();
        }

        uint32_t sb = base + (s % 3)*STAGEF;
#pragma unroll
        for (int kk = 0; kk < 4; kk++){
            uint32_t af[2][4];
#pragma unroll
            for (int f=0; f<2; f++){
                int arow = wm*32 + f*16 + (lane & 7) + ((lane >> 3) & 1)*8;
                uint32_t ab = sw128((uint32_t)(arow*128 + kk*32 + (lane >> 4)*16));
                LDSM_X4(af[f][0],af[f][1],af[f][2],af[f][3], sb + ab);
            }
            uint32_t bfrag[8][2];
#pragma unroll
            for (int g=0; g<4; g++){
                int nrow = wn*64 + g*16 + (lane & 7) + ((lane >> 4) << 3);
                uint32_t bb = sw128((uint32_t)(nrow*128 + kk*32 + ((lane >> 3) & 1)*16));
                uint32_t r0,r1,r2,r3;
                LDSM_X4(r0,r1,r2,r3, sb + TILE16 + bb);
                bfrag[2*g][0]=r0; bfrag[2*g][1]=r1; bfrag[2*g+1][0]=r2; bfrag[2*g+1][1]=r3;
            }
#pragma unroll
            for (int f=0; f<2; f++)
#pragma unroll
                for (int j=0; j<8; j++)
                    MMAF16(acc[f][j], af[f], bfrag[j]);
        }
    }

#pragma unroll
    for (int f=0; f<2; f++){
        int r = m0 + wm*32 + f*16 + (lane >> 2);
#pragma unroll
        for (int j=0; j<8; j++){
            int cc = n0 + wn*64 + j*8 + (lane & 3)*2;
            *(float2*)&C[(size_t)r*Dm + cc]     = make_float2(acc[f][j][0], acc[f][j][1]);
            *(float2*)&C[(size_t)(r+8)*Dm + cc] = make_float2(acc[f][j][2], acc[f][j][3]);
        }
    }
}

// ================= X -> fp16 =================
__global__ void tohalf_kernel(const float* __restrict__ src, __half* __restrict__ dst)
{
    int i = blockIdx.x * blockDim.x + threadIdx.x;
    float4 v = ((const float4*)src)[i];
    uint2 o;
    o.x = f2h2(v.x, v.y);
    o.y = f2h2(v.z, v.w);
    ((uint2*)dst)[i] = o;
}

// 4 matrices W [K][N] -> Wt [N][K] fp16, z selects
__global__ void wsplit_kernel(const float* __restrict__ W0, const float* __restrict__ W1,
                              const float* __restrict__ W2, const float* __restrict__ W3,
                              __half* __restrict__ thBase)
{
    __shared__ float tile[32][33];
    int z = blockIdx.z;
    const float* W = (z==0)?W0:((z==1)?W1:((z==2)?W2:W3));
    __half* th = thBase + (size_t)z*Dm*Dm;
    int n0 = blockIdx.x * 32, k0 = blockIdx.y * 32;
    int tx = threadIdx.x, ty = threadIdx.y;
    for (int r = ty; r < 32; r += 8) tile[r][tx] = W[(size_t)(k0 + r) * Dm + n0 + tx];
    __syncthreads();
    for (int r = ty; r < 32; r += 8)
        th[(size_t)(n0 + r) * Dm + k0 + tx] = __float2half(tile[tx][r]);
}

// ---------------- small projections ----------------
__global__ __launch_bounds__(256) void proj_small_kernel(const float* __restrict__ X,
                                                         const float* __restrict__ Wb_,
                                                         const float* __restrict__ Wd_,
                                                         const float* __restrict__ Wm_)
{
    __shared__ float4 wb[256], wd[256], wm[256];
    int tid = threadIdx.x, lane = tid & 31, wid = tid >> 5;
    int t = blockIdx.x * 8 + wid;
    float acc[12];
#pragma unroll
    for (int i=0;i<12;i++) acc[i]=0.0f;
    for (int e0 = 0; e0 < 1024; e0 += 256){
        __syncthreads();
        wb[tid] = ((const float4*)Wb_)[e0 + tid];
        wd[tid] = ((const float4*)Wd_)[e0 + tid];
        wm[tid] = ((const float4*)Wm_)[e0 + tid];
        __syncthreads();
        for (int e = lane; e < 256; e += 32){
            float xv = X[(size_t)t*Dm + e0 + e];
            float4 b = wb[e], d = wd[e], m = wm[e];
            acc[0]+=xv*b.x; acc[1]+=xv*b.y; acc[2]+=xv*b.z; acc[3]+=xv*b.w;
            acc[4]+=xv*d.x; acc[5]+=xv*d.y; acc[6]+=xv*d.z; acc[7]+=xv*d.w;
            acc[8]+=xv*m.x; acc[9]+=xv*m.y; acc[10]+=xv*m.z; acc[11]+=xv*m.w;
        }
    }
#pragma unroll
    for (int i=0;i<12;i++){
        float s = acc[i];
        for (int o=16;o;o>>=1) s += __shfl_xor_sync(0xffffffffu, s, o);
        acc[i] = s;
    }
    if (lane == 0){
#pragma unroll
        for (int c=0;c<4;c++){
            g_beta [t*Hh+c] = sigm(acc[c]);
            g_gamma[t*Hh+c] = sigm(acc[4+c]);
            g_mixlin[t*Hh+c] = acc[8+c];
        }
    }
}

__global__ void conv_mix_kernel(const float* __restrict__ cm, const float* __restrict__ mbias)
{
    int e = blockIdx.x*blockDim.x + threadIdx.x;
    if (e >= Mrows*Hh) return;
    int t = e / Hh, h = e % Hh;
    int tl = t % Lseq;
    float w0=cm[h*4+0], w1=cm[h*4+1], w2=cm[h*4+2], w3=cm[h*4+3];
    float acc = g_mixlin[e]*w3;
    if (tl>=1) acc += g_mixlin[e-Hh]*w2;
    if (tl>=2) acc += g_mixlin[e-2*Hh]*w1;
    if (tl>=3) acc += g_mixlin[e-3*Hh]*w0;
    float y = acc * sigm(acc);
    g_mix[e] = sigm(y + mbias[h]);
}

// ---------------- per-chunk precompute: fused conv+silu + everything ----------
#define SQS 260
__global__ __launch_bounds__(256) void chunk_pre_kernel(
    const float* __restrict__ cq, const float* __restrict__ ck, const float* __restrict__ cv)
{
    extern __shared__ float sm4[];
    float* sq  = sm4;
    float* skk = sq  + 32*SQS;
    float* sv  = skk + 32*SQS;
    float* sT  = sv  + 32*SQS;
    float* sb  = sT  + 1024;
    float* sg  = sb  + 32;
    int z = blockIdx.x;
    int b  = z >> 8;
    int h  = (z >> 6) & 3;
    int nc = z & 63;
    int t0 = b*Lseq + nc*CHK;
    int cb = h*DHd;
    int tid = threadIdx.x, lane = tid & 31, wid = tid >> 5;

    // phase 1: fused causal conv + silu from *lin buffers into sq/skk/sv.
    // 192 strips: tensor s (0..2) x colgroup g (0..63), 4 channels each.
    if (tid < 192){
        int s = tid >> 6;        // 0=q,1=k,2=v
        int g = tid & 63;
        const float* lin = (s==0) ? g_qlin : ((s==1) ? g_klin : g_vlin);
        const float* cw  = (s==0) ? cq     : ((s==1) ? ck     : cv);
        float* dst       = (s==0) ? sq     : ((s==1) ? skk    : sv);
        int dsilu = (s < 2);
        int cg4 = (cb >> 2) + g;              // float4 column index
        int cch = cb + g*4;                   // channel base

        float4 wv0 = ((const float4*)cw)[cch+0];
        float4 wv1 = ((const float4*)cw)[cch+1];
        float4 wv2 = ((const float4*)cw)[cch+2];
        float4 wv3 = ((const float4*)cw)[cch+3];

        const int strd = Dm/4;
        const float4* L = (const float4*)lin + (size_t)t0*strd + cg4;

        float4 h1,h2,h3;
        if (nc == 0){
            h1 = h2 = h3 = make_float4(0,0,0,0);
        } else {
            h1 = L[-1*strd]; h2 = L[-2*strd]; h3 = L[-3*strd];
        }
#pragma unroll 4
        for (int i=0;i<CHK;i++){
            float4 x = L[i*strd];
            float4 a;
            a.x = x.x*wv0.w + h1.x*wv0.z + h2.x*wv0.y + h3.x*wv0.x;
            a.y = x.y*wv1.w + h1.y*wv1.z + h2.y*wv1.y + h3.y*wv1.x;
            a.z = x.z*wv2.w + h1.z*wv2.z + h2.z*wv2.y + h3.z*wv2.x;
            a.w = x.w*wv3.w + h1.w*wv3.z + h2.w*wv3.y + h3.w*wv3.x;
            h3 = h2; h2 = h1; h1 = x;
            float4 y;
            y.x = a.x * sigm(a.x); y.y = a.y * sigm(a.y);
            y.z = a.z * sigm(a.z); y.w = a.w * sigm(a.w);
            if (dsilu){
                y.x = y.x * sigm(y.x); y.y = y.y * sigm(y.y);
                y.z = y.z * sigm(y.z); y.w = y.w * sigm(y.w);
            }
            *(float4*)&dst[i*SQS + g*4] = y;
        }
    } else if (tid < 224){
        sb[tid-192] = g_beta[(t0+tid-192)*Hh + h];
    } else {
        sg[tid-224] = g_gamma[(t0+tid-224)*Hh + h];
    }
    __syncthreads();

    for (int r=wid; r<32; r+=8){
        float s=0.0f;
        for (int c=lane;c<256;c+=32){ float v=sq[r*SQS+c]; s+=v*v; }
        for (int o=16;o;o>>=1) s += __shfl_xor_sync(0xffffffffu,s,o);
        float rn = rsqrtf(s + 1e-6f);
        for (int c=lane;c<256;c+=32){ sq[r*SQS+c] *= rn; }
        s=0.0f;
        for (int c=lane;c<256;c+=32){ float v=skk[r*SQS+c]; s+=v*v; }
        for (int o=16;o;o>>=1) s += __shfl_xor_sync(0xffffffffu,s,o);
        rn = rsqrtf(s + 1e-6f);
        for (int c=lane;c<256;c+=32){ skk[r*SQS+c] *= rn; }
    }
    __syncthreads();

    {
        int ti = tid >> 4, tj = tid & 15;
        int i0 = 2*ti, j0 = 2*tj;
        float a00=0,a01=0,a10=0,a11=0;
        float q00=0,q01=0,q10=0,q11=0;
#pragma unroll 8
        for (int p=0;p<256;p+=4){
            float4 ki0 = *(float4*)&skk[i0*SQS+p];
            float4 ki1 = *(float4*)&skk[(i0+1)*SQS+p];
            float4 qi0 = *(float4*)&sq [i0*SQS+p];
            float4 qi1 = *(float4*)&sq [(i0+1)*SQS+p];
            float4 kj0 = *(float4*)&skk[j0*SQS+p];
            float4 kj1 = *(float4*)&skk[(j0+1)*SQS+p];
            a00 += ki0.x*kj0.x + ki0.y*kj0.y + ki0.z*kj0.z + ki0.w*kj0.w;
            a01 += ki0.x*kj1.x + ki0.y*kj1.y + ki0.z*kj1.z + ki0.w*kj1.w;
            a10 += ki1.x*kj0.x + ki1.y*kj0.y + ki1.z*kj0.z + ki1.w*kj0.w;
            a11 += ki1.x*kj1.x + ki1.y*kj1.y + ki1.z*kj1.z + ki1.w*kj1.w;
            q00 += qi0.x*kj0.x + qi0.y*kj0.y + qi0.z*kj0.z + qi0.w*kj0.w;
            q01 += qi0.x*kj1.x + qi0.y*kj1.y + qi0.z*kj1.z + qi0.w*kj1.w;
            q10 += qi1.x*kj0.x + qi1.y*kj0.y + qi1.z*kj0.z + qi1.w*kj0.w;
            q11 += qi1.x*kj1.x + qi1.y*kj1.y + qi1.z*kj1.z + qi1.w*kj1.w;
        }
        sT[i0*32+j0]       = (j0   < i0  ) ? -sb[i0]*a00   : 0.0f;
        sT[i0*32+j0+1]     = (j0+1 < i0  ) ? -sb[i0]*a01   : 0.0f;
        sT[(i0+1)*32+j0]   = (j0   < i0+1) ? -sb[i0+1]*a10 : 0.0f;
        sT[(i0+1)*32+j0+1] = (j0+1 < i0+1) ? -sb[i0+1]*a11 : 0.0f;
        size_t abase = (size_t)z*1024;
        g_A2[abase + i0*32+j0]       = (j0   <= i0  ) ? q00 : 0.0f;
        g_A2[abase + i0*32+j0+1]     = (j0+1 <= i0  ) ? q01 : 0.0f;
        g_A2[abase + (i0+1)*32+j0]   = (j0   <= i0+1) ? q10 : 0.0f;
        g_A2[abase + (i0+1)*32+j0+1] = (j0+1 <= i0+1) ? q11 : 0.0f;
    }
    __syncthreads();

    // fwd-subst on warp 0; warps 1-7 write k^T fp16 concurrently
    size_t ktb = (size_t)z*8192;
    if (wid == 0){
        for (int i=1;i<32;i++){
            float a = sT[i*32+lane];
            float acc = 0.0f;
            for (int j=1;j<32;j++){
                float aij = __shfl_sync(0xffffffffu, a, j);
                acc += aij * sT[j*32+lane];
            }
            if (lane < i) sT[i*32+lane] = a + acc;
            __syncwarp();
        }
        sT[lane*32+lane] += 1.0f;
    } else {
        for (int e=tid-32; e<8192; e+=224){
            int r=e>>5, j=e&31;
            g_kt16[ktb + r*32 + j] = __float2half(skk[j*SQS + r]);
        }
    }
    __syncthreads();

    for (int e=tid; e<1024; e+=256) sT[e] *= sb[e&31];
    __syncthreads();

    size_t wqb = (size_t)z*16384;
    {
        int ri = tid >> 6;
        int tc = (tid & 63) * 4;
        float4 ua[8], wa[8];
#pragma unroll
        for (int r=0;r<8;r++){ ua[r]=make_float4(0,0,0,0); wa[r]=make_float4(0,0,0,0); }
        for (int j=0;j<32;j++){
            float4 v4 = *(float4*)&sv [j*SQS + tc];
            float4 k4 = *(float4*)&skk[j*SQS + tc];
#pragma unroll
            for (int r=0;r<8;r++){
                float tb = sT[(ri*8+r)*32 + j];
                ua[r].x += tb*v4.x; ua[r].y += tb*v4.y; ua[r].z += tb*v4.z; ua[r].w += tb*v4.w;
                wa[r].x += tb*k4.x; wa[r].y += tb*k4.y; wa[r].z += tb*k4.z; wa[r].w += tb*k4.w;
            }
        }
#pragma unroll
        for (int r=0;r<8;r++){
            int i = ri*8 + r;
            *(float4*)&g_u[(size_t)(t0+i)*Dm + cb + tc] = ua[r];
            *(uint2*)&g_wq16[wqb + i*256 + tc] = make_uint2(f2h2(wa[r].x, wa[r].y), f2h2(wa[r].z, wa[r].w));
            float4 q4 = *(float4*)&sq[i*SQS + tc];
            *(uint2*)&g_wq16[wqb + (32+i)*256 + tc] = make_uint2(f2h2(q4.x, q4.y), f2h2(q4.z, q4.w));
        }
    }

    {
        int c = tid;
        float s = 0.0f, pg = 1.0f;
#pragma unroll
        for (int t=0;t<CHK;t++){
            float g = sg[t];
            s = g*s + (1.0f-g)*sv[t*SQS + c];
            pg *= g;
            g_ema[(size_t)(t0+t)*Dm + cb + c] = s;
            if (c == 0) g_pg[(t0+t)*Hh + h] = pg;
        }
    }
}

// ---------------- fp16 MMA recurrence, dv-sliced, double-buffered ----------------
__global__ __launch_bounds__(256) void recurrence_kernel()
{
    extern __shared__ char sm5[];
    uint32_t raw = smem_u32(sm5);
    uint32_t base = (raw + 127u) & ~127u;
    char* p0 = sm5 + (base - raw);

    const uint32_t oWQ0=0, oWQ1=32768;
    const uint32_t oKT0=65536, oKT1=86016;
    const uint32_t oSh=106496, oSl=126976;
    const uint32_t oUA=147456;
    const uint32_t oU0=150016, oU1=154624;
    const uint32_t oA20=159232, oA21=163840;
    const uint32_t oRq=168448, oUA32=173056;

    float* Rq_s = (float*)(p0 + oRq);
    float* ua_s = (float*)(p0 + oUA32);
    char* pSh = p0 + oSh; char* pSl = p0 + oSl;
    char* pUA = p0 + oUA;
    uint32_t uSh = base+oSh, uSl = base+oSl, uUA = base+oUA;

    int bx = blockIdx.x;
    int bh = bx >> 3, vb = bx & 7;
    int b = bh >> 2, h = (bx >> 3) & 3;
    int cvb = h*DHd + vb*32;
    int tid = threadIdx.x, lane = tid & 31, wid = tid >> 5;
    int rm = wid >> 1, rn = wid & 1;

    float accS[2][4][4];
#pragma unroll
    for (int tm=0;tm<2;tm++)
#pragma unroll
        for (int tn=0;tn<4;tn++)
#pragma unroll
            for (int e=0;e<4;e++) accS[tm][tn][e]=0.0f;

    auto load_chunk = [&](int cc, int sl){
        int slot = bh*NCk + cc;
        int tt0 = b*Lseq + cc*CHK;
        const __half* gwq = g_wq16 + (size_t)slot*16384;
        const __half* gkt = g_kt16 + (size_t)slot*8192;
        uint32_t uWQ = base + (sl ? oWQ1 : oWQ0);
        uint32_t uKT = base + (sl ? oKT1 : oKT0);
        uint32_t uU  = base + (sl ? oU1  : oU0);
        uint32_t uA2 = base + (sl ? oA21 : oA20);
#pragma unroll
        for (int t=0;t<8;t++){
            int c = tid + t*256;
            int row = c >> 5, col = c & 31;
            cpa16(uWQ + row*512 + ((uint32_t)(col ^ (row & 7)) << 4), gwq + c*8);
        }
#pragma unroll
        for (int t=0;t<4;t++){
            int c = tid + t*256;
            int row = c >> 2, col = c & 3;
            cpa16(uKT + row*80 + (col << 4), gkt + c*8);
        }
        {
            int row = tid >> 3, col = tid & 7;
            cpa16(uU + row*144 + col*16, &g_u[(size_t)(tt0+row)*Dm + cvb + col*4]);
            cpa16(uA2 + row*144 + col*16, g_A2 + (size_t)slot*1024 + tid*4);
        }
        CP_COMMIT();
    };

    load_chunk(0, 0);

    for (int ci=0; ci<NCk; ci++){
        __syncthreads();
        int sl = ci & 1;
        int t0 = b*Lseq + ci*CHK;
        uint32_t uWQ = base + (sl ? oWQ1 : oWQ0);
        uint32_t uKT = base + (sl ? oKT1 : oKT0);
        float* u_s  = (float*)(p0 + (sl ? oU1  : oU0));
        float* A2_s = (float*)(p0 + (sl ? oA21 : oA20));

        if (ci+1 < NCk) load_chunk(ci+1, (ci+1)&1);

#pragma unroll
        for (int tm=0;tm<2;tm++)
#pragma unroll
        for (int tn=0;tn<4;tn++){
            int r = wid*32 + tm*16 + (lane>>2);
            int c = tn*8 + (lane&3)*2;
            uint32_t hw, lw;
            split2h(accS[tm][tn][0], accS[tm][tn][1], hw, lw);
            *(uint32_t*)(pSh + r*80 + c*2) = hw;
            *(uint32_t*)(pSl + r*80 + c*2) = lw;
            split2h(accS[tm][tn][2], accS[tm][tn][3], hw, lw);
            *(uint32_t*)(pSh + (r+8)*80 + c*2) = hw;
            *(uint32_t*)(pSl + (r+8)*80 + c*2) = lw;
        }

        if (ci == NCk-1) { CP_WAIT(0); } else { CP_WAIT(1); }
        __syncthreads();

        float accR[2][4];
#pragma unroll
        for (int j=0;j<2;j++)
#pragma unroll
            for (int e=0;e<4;e++) accR[j][e]=0.0f;

#pragma unroll 4
        for (int kk=0; kk<16; kk++){
            int arow = rm*16 + (lane & 7) + ((lane >> 3) & 1)*8;
            int achunk = kk*2 + (lane >> 4);
            uint32_t af[4];
            LDSM_X4(af[0],af[1],af[2],af[3], uWQ + arow*512 + ((uint32_t)(achunk ^ (arow & 7)) << 4));

            int krow = kk*16 + (lane & 7) + ((lane >> 3) & 1)*8;
            uint32_t boff = krow*80 + rn*32 + ((lane >> 4) << 4);
            uint32_t s0,s1,s2,s3;
            LDSM_X4T(s0,s1,s2,s3, uSh + boff);
            uint32_t bh0[2] = {s0,s1}, bh1[2] = {s2,s3};
            LDSM_X4T(s0,s1,s2,s3, uSl + boff);
            uint32_t bl0[2] = {s0,s1}, bl1[2] = {s2,s3};

            MMAF16(accR[0], af, bh0);
            MMAF16(accR[0], af, bl0);
            MMAF16(accR[1], af, bh1);
            MMAF16(accR[1], af, bl1);
        }

        if (wid < 4){
#pragma unroll
            for (int j=0;j<2;j++){
                int c = rn*16 + j*8 + (lane&3)*2;
                int r1 = rm*16 + (lane>>2);
                float ua0 = u_s[r1*36+c]   - accR[j][0];
                float ua1 = u_s[r1*36+c+1] - accR[j][1];
                *(uint32_t*)(pUA + r1*80 + c*2) = f2h2(ua0, ua1);
                *(float2*)&ua_s[r1*36+c] = make_float2(ua0, ua1);
                float ua2 = u_s[(r1+8)*36+c]   - accR[j][2];
                float ua3 = u_s[(r1+8)*36+c+1] - accR[j][3];
                *(uint32_t*)(pUA + (r1+8)*80 + c*2) = f2h2(ua2, ua3);
                *(float2*)&ua_s[(r1+8)*36+c] = make_float2(ua2, ua3);
            }
        } else {
#pragma unroll
            for (int j=0;j<2;j++){
                int c = rn*16 + j*8 + (lane&3)*2;
                int r1 = (rm-2)*16 + (lane>>2);
                *(float2*)&Rq_s[r1*36+c]     = make_float2(accR[j][0], accR[j][1]);
                *(float2*)&Rq_s[(r1+8)*36+c] = make_float2(accR[j][2], accR[j][3]);
            }
        }
        __syncthreads();

        {
            int c = tid & 31, rb = tid >> 5;
            float o0 = Rq_s[rb*36+c], o1 = Rq_s[(rb+8)*36+c];
            float o2 = Rq_s[(rb+16)*36+c], o3 = Rq_s[(rb+24)*36+c];
#pragma unroll 8
            for (int j=0;j<32;j++){
                float uv = ua_s[j*36+c];
                o0 += A2_s[rb*36+j]*uv;
                o1 += A2_s[(rb+8)*36+j]*uv;
                o2 += A2_s[(rb+16)*36+j]*uv;
                o3 += A2_s[(rb+24)*36+j]*uv;
            }
            g_od[(size_t)(t0+rb)*Dm + cvb + c]      = o0;
            g_od[(size_t)(t0+rb+8)*Dm + cvb + c]    = o1;
            g_od[(size_t)(t0+rb+16)*Dm + cvb + c]   = o2;
            g_od[(size_t)(t0+rb+24)*Dm + cvb + c]   = o3;
        }

#pragma unroll
        for (int kk=0; kk<2; kk++){
            uint32_t a_f[2][4];
#pragma unroll
            for (int tm=0;tm<2;tm++){
                int mrow = wid*32 + tm*16 + (lane & 7) + ((lane >> 3) & 1)*8;
                LDSM_X4(a_f[tm][0],a_f[tm][1],a_f[tm][2],a_f[tm][3],
                        uKT + mrow*80 + kk*32 + ((lane >> 4) << 4));
            }
            uint32_t bu[4][2];
#pragma unroll
            for (int g=0; g<2; g++){
                int krow = kk*16 + (lane & 7) + ((lane >> 3) & 1)*8;
                uint32_t r0,r1,r2,r3;
                LDSM_X4T(r0,r1,r2,r3, uUA + krow*80 + g*32 + ((lane >> 4) << 4));
                bu[2*g][0]=r0; bu[2*g][1]=r1; bu[2*g+1][0]=r2; bu[2*g+1][1]=r3;
            }
#pragma unroll
            for (int tm=0;tm<2;tm++)
#pragma unroll
                for (int tn=0;tn<4;tn++)
                    MMAF16(accS[tm][tn], a_f[tm], bu[tn]);
        }
    }
}

// ---------------- EMA cross-chunk scan ------------
__global__ void ema_seq_kernel()
{
    extern __shared__ float sE[];
    float* sP = sE + NCk*DHd;
    int bh = blockIdx.x;
    int b = bh >> 2, h = bh & 3;
    int cb = h*DHd;
    int tid = threadIdx.x;

    for (int i = tid; i < NCk*DHd; i += 256){
        int j = i >> 8, col = i & 255;
        sE[i] = g_ema[(size_t)(b*Lseq + j*CHK + CHK-1)*Dm + cb + col];
    }
    if (tid < NCk) sP[tid] = g_pg[(b*Lseq + tid*CHK + CHK-1)*Hh + h];
    __syncthreads();

    int c = tid;
    float S = 0.0f;
    for (int j=0;j<NCk;j++){
        g_sst[(size_t)(bh*NCk + j)*DHd + c] = S;
        S = sE[j*DHd + c] + sP[j]*S;
    }
}

// ---------------- mix + rmsnorm -> fp16 output ----------------
__global__ __launch_bounds__(256) void combine_kernel(const float* __restrict__ rmsw)
{
    int t = blockIdx.x, c = threadIdx.x;
    int lane = c & 31, w = c >> 5;
    int b = t / Lseq, tl = t % Lseq, chunk = tl >> 5;
    __shared__ float red[4][8];
    float o[4];
#pragma unroll
    for (int h=0;h<Hh;h++){
        float mix = g_mix[t*Hh+h];
        size_t idx = (size_t)t*Dm + h*DHd + c;
        float ema = g_ema[idx] + g_pg[t*Hh+h] * g_sst[(size_t)((b*4+h)*NCk + chunk)*DHd + c];
        o[h] = (1.0f-mix)*g_od[idx] + mix*ema;
        float s = o[h]*o[h];
        for (int off=16;off;off>>=1) s += __shfl_xor_sync(0xffffffffu,s,off);
        if (lane==0) red[h][w]=s;
    }
    __syncthreads();
#pragma unroll
    for (int h=0;h<Hh;h++){
        float tot = red[h][0]+red[h][1]+red[h][2]+red[h][3]+red[h][4]+red[h][5]+red[h][6]+red[h][7];
        float scale = rsqrtf(tot*(1.0f/256.0f) + 1e-5f);
        g_oc16[(size_t)t*Dm + h*DHd + c] = __float2half(o[h]*scale*rmsw[c]);
    }
}

// ---------------- launcher ----------------
extern "C" void kernel_launch(void* const* d_in, const int* in_sizes, int n_in,
                              void* d_out, int out_size)
{
    const float* X    = (const float*)d_in[0];
    const float* Wq   = (const float*)d_in[1];
    const float* Wk   = (const float*)d_in[2];
    const float* Wv   = (const float*)d_in[3];
    const float* cq   = (const float*)d_in[4];
    const float* ck   = (const float*)d_in[5];
    const float* cv   = (const float*)d_in[6];
    const float* Wb   = (const float*)d_in[7];
    const float* Wdec = (const float*)d_in[8];
    const float* Wmix = (const float*)d_in[9];
    const float* cmix = (const float*)d_in[10];
    const float* mbias= (const float*)d_in[11];
    const float* rmsw = (const float*)d_in[12];
    const float* Wo   = (const float*)d_in[13];
    float* out = (float*)d_out;
    (void)in_sizes; (void)n_in; (void)out_size;

    float *p_qlin,*p_klin,*p_vlin;
    __half *p_x16,*p_oc16,*p_wt16;
    cudaGetSymbolAddress((void**)&p_qlin, g_qlin);
    cudaGetSymbolAddress((void**)&p_klin, g_klin);
    cudaGetSymbolAddress((void**)&p_vlin, g_vlin);
    cudaGetSymbolAddress((void**)&p_x16,  g_x16);
    cudaGetSymbolAddress((void**)&p_oc16, g_oc16);
    cudaGetSymbolAddress((void**)&p_wt16, g_wt16);

    static cudaStream_t s2 = nullptr;
    static cudaEvent_t evFork = nullptr, evW = nullptr, evProj = nullptr, evPre = nullptr, evEma = nullptr;
    if (!s2){
        cudaStreamCreateWithFlags(&s2, cudaStreamNonBlocking);
        cudaEventCreateWithFlags(&evFork, cudaEventDisableTiming);
        cudaEventCreateWithFlags(&evW,    cudaEventDisableTiming);
        cudaEventCreateWithFlags(&evProj, cudaEventDisableTiming);
        cudaEventCreateWithFlags(&evPre,  cudaEventDisableTiming);
        cudaEventCreateWithFlags(&evEma,  cudaEventDisableTiming);
    }

    const int SMEMG = 3*STAGEF + 256;
    cudaFuncSetAttribute(mma_gemm_kernel, cudaFuncAttributeMaxDynamicSharedMemorySize, SMEMG);

    // side stream: wsplit first (needed by GEMM), then proj_small + conv_mix
    cudaEventRecord(evFork, 0);
    cudaStreamWaitEvent(s2, evFork, 0);
    dim3 wg(32,32,4), wb2(32,8);
    wsplit_kernel<<<wg,wb2,0,s2>>>(Wq, Wk, Wv, Wo, p_wt16);
    cudaEventRecord(evW, s2);
    proj_small_kernel<<<Mrows/8,256,0,s2>>>(X, Wb, Wdec, Wmix);
    conv_mix_kernel<<<(Mrows*Hh+255)/256,256,0,s2>>>(cmix, mbias);
    cudaEventRecord(evProj, s2);

    // main chain
    tohalf_kernel<<<MD/4/256,256>>>(X, p_x16);
    cudaStreamWaitEvent(0, evW, 0);

    dim3 gg3(Dm/128, Mrows/128, 3);
    mma_gemm_kernel<<<gg3,256,SMEMG>>>(p_x16, p_wt16, 0, p_qlin, p_klin, p_vlin);

    // chunk_pre (with fused conv+silu) needs beta/gamma from the side stream
    cudaStreamWaitEvent(0, evProj, 0);

    const int SMEM4 = (3*32*SQS + 1024 + 64) * 4;
    cudaFuncSetAttribute(chunk_pre_kernel, cudaFuncAttributeMaxDynamicSharedMemorySize, SMEM4);
    chunk_pre_kernel<<<Bb*Hh*NCk, 256, SMEM4>>>(cq, ck, cv);
    cudaEventRecord(evPre, 0);

    cudaStreamWaitEvent(s2, evPre, 0);
    const int SMEME = (NCk*DHd + NCk) * 4;
    cudaFuncSetAttribute(ema_seq_kernel, cudaFuncAttributeMaxDynamicSharedMemorySize, SMEME);
    ema_seq_kernel<<<Bb*Hh, 256, SMEME, s2>>>();
    cudaEventRecord(evEma, s2);

    const int SMEM5 = 177664 + 256;
    cudaFuncSetAttribute(recurrence_kernel, cudaFuncAttributeMaxDynamicSharedMemorySize, SMEM5);
    recurrence_kernel<<<Bb*Hh*8, 256, SMEM5>>>();

    cudaStreamWaitEvent(0, evEma, 0);
    combine_kernel<<<Mrows,256>>>(rmsw);

    dim3 gg1(Dm/128, Mrows/128, 1);
    mma_gemm_kernel<<<gg1,256,SMEMG>>>(p_oc16, p_wt16, 3, out, out, out);
}

// round 13
// speedup vs baseline: 1.6572x; 1.6572x over previous
#include <cuda_runtime.h>
#include <cuda_fp16.h>
#include <math.h>
#include <stdint.h>

#define Bb   4
#define Lseq 2048
#define Dm   1024
#define Hh   4
#define DHd  256
#define CHK  32
#define NCk  (Lseq/CHK)      // 64
#define Mrows (Bb*Lseq)      // 8192
#define MD (Mrows*Dm)

// ---------------- scratch ----------------
__device__ float g_qlin[MD], g_klin[MD], g_vlin[MD];
__device__ float g_q[MD], g_k[MD], g_v[MD];
__device__ float g_u[MD];
__device__ float g_A2[Bb*Hh*NCk*CHK*CHK];
__device__ float g_beta[Mrows*Hh], g_gamma[Mrows*Hh], g_mixlin[Mrows*Hh], g_mix[Mrows*Hh];
__device__ float g_od[MD], g_ema[MD];
__device__ float g_pg[Mrows*Hh];
__device__ float g_sst[Bb*Hh*NCk*DHd];
__device__ __half g_x16[MD];
__device__ __half g_oc16[MD];
__device__ __half g_wt16[4*Dm*Dm];
__device__ __half g_wq16[Bb*Hh*NCk*64*256];
__device__ __half g_kt16[Bb*Hh*NCk*256*32];

__device__ __forceinline__ float sigm(float x){ return 1.0f/(1.0f+__expf(-x)); }

__device__ __forceinline__ uint32_t smem_u32(const void* p){
    uint32_t a;
    asm("{ .reg .u64 t; cvta.to.shared.u64 t, %1; cvt.u32.u64 %0, t; }" : "=r"(a) : "l"(p));
    return a;
}
__device__ __forceinline__ uint32_t sw128(uint32_t b){ return b ^ ((b >> 3) & 0x70); }

__device__ __forceinline__ void cpa16(uint32_t dst, const void* src){
    asm volatile("cp.async.cg.shared.global [%0], [%1], 16;" :: "r"(dst), "l"(src) : "memory");
}
#define CP_COMMIT() asm volatile("cp.async.commit_group;" ::: "memory")
#define CP_WAIT(n)  asm volatile("cp.async.wait_group %0;" :: "n"(n) : "memory")

#define LDSM_X4(r0,r1,r2,r3, addr) \
    asm volatile("ldmatrix.sync.aligned.m8n8.x4.shared.b16 {%0,%1,%2,%3}, [%4];" \
        : "=r"(r0),"=r"(r1),"=r"(r2),"=r"(r3) : "r"(addr))
#define LDSM_X4T(r0,r1,r2,r3, addr) \
    asm volatile("ldmatrix.sync.aligned.m8n8.x4.trans.shared.b16 {%0,%1,%2,%3}, [%4];" \
        : "=r"(r0),"=r"(r1),"=r"(r2),"=r"(r3) : "r"(addr))

#define MMAF16(d, a, b) \
    asm volatile("mma.sync.aligned.m16n8k16.row.col.f32.f16.f16.f32 " \
        "{%0,%1,%2,%3}, {%4,%5,%6,%7}, {%8,%9}, {%0,%1,%2,%3};" \
        : "+f"((d)[0]),"+f"((d)[1]),"+f"((d)[2]),"+f"((d)[3]) \
        : "r"((a)[0]),"r"((a)[1]),"r"((a)[2]),"r"((a)[3]), "r"((b)[0]),"r"((b)[1]))

__device__ __forceinline__ uint32_t f2h2(float a, float b){
    __half2 h = __floats2half2_rn(a, b);
    return *(uint32_t*)&h;
}
__device__ __forceinline__ void split2h(float a, float b, uint32_t &hi, uint32_t &lo){
    __half ah = __float2half(a), bh = __float2half(b);
    __half al = __float2half(a - __half2float(ah));
    __half bl = __float2half(b - __half2float(bh));
    hi = ((uint32_t)*(uint16_t*)&bh << 16) | *(uint16_t*)&ah;
    lo = ((uint32_t)*(uint16_t*)&bl << 16) | *(uint16_t*)&al;
}

// ================= fp16 HMMA GEMM: 128x128 tile, BK=64, 3 stages, single-sync ===
#define TILE16 16384
#define STAGEF (2*TILE16)

__global__ __launch_bounds__(256,2) void mma_gemm_kernel(
    const __half* __restrict__ A,
    const __half* __restrict__ BtBase,
    int woff, float* __restrict__ C0, float* __restrict__ C1, float* __restrict__ C2)
{
    extern __shared__ char dyn[];
    uint32_t raw = smem_u32(dyn);
    uint32_t base = (raw + 127u) & ~127u;

    int z = blockIdx.z;
    const __half* Bt = BtBase + (size_t)(woff + z) * Dm * Dm;
    float* C = (z == 0) ? C0 : ((z == 1) ? C1 : C2);

    int tid = threadIdx.x, lane = tid & 31, wid = tid >> 5;
    int wm = wid >> 1, wn = wid & 1;
    int m0 = blockIdx.y * 128, n0 = blockIdx.x * 128;

    const __half* gA = A  + (size_t)m0 * Dm;
    const __half* gB = Bt + (size_t)n0 * Dm;

    float acc[2][8][4];
#pragma unroll
    for (int f=0; f<2; f++)
#pragma unroll
        for (int j=0; j<8; j++)
#pragma unroll
            for (int e=0; e<4; e++) acc[f][j][e] = 0.0f;

    const int NSTEP = Dm / 64;   // 16

#pragma unroll
    for (int ps=0; ps<2; ps++){
        uint32_t sb = base + ps*STAGEF;
        int k0 = ps*64;
#pragma unroll
        for (int t=0;t<4;t++){
            int c = tid + t*256;
            int row = c >> 3, col = c & 7;
            size_t go = (size_t)row*Dm + k0 + col*8;
            uint32_t so = sw128((uint32_t)(row*128 + col*16));
            cpa16(sb + so,          gA + go);
            cpa16(sb + TILE16 + so, gB + go);
        }
        CP_COMMIT();
    }

    for (int s = 0; s < NSTEP; s++){
        if (s == NSTEP-1) { CP_WAIT(0); } else { CP_WAIT(1); }
        __syncthreads();

        if (s+2 < NSTEP){
            uint32_t nb = base + ((s+2) % 3)*STAGEF;
            int k0 = (s+2)*64;
#pragma unroll
            for (int t=0;t<4;t++){
                int c = tid + t*256;
                int row = c >> 3, col = c & 7;
                size_t go = (size_t)row*Dm + k0 + col*8;
                uint32_t so = sw128((uint32_t)(row*128 + col*16));
                cpa16(nb + so,          gA + go);
                cpa16(nb + TILE16 + so, gB + go);
            }
            CP_COMMIT();
        }

        uint32_t sb = base + (s % 3)*STAGEF;
#pragma unroll
        for (int kk = 0; kk < 4; kk++){
            uint32_t af[2][4];
#pragma unroll
            for (int f=0; f<2; f++){
                int arow = wm*32 + f*16 + (lane & 7) + ((lane >> 3) & 1)*8;
                uint32_t ab = sw128((uint32_t)(arow*128 + kk*32 + (lane >> 4)*16));
                LDSM_X4(af[f][0],af[f][1],af[f][2],af[f][3], sb + ab);
            }
            uint32_t bfrag[8][2];
#pragma unroll
            for (int g=0; g<4; g++){
                int nrow = wn*64 + g*16 + (lane & 7) + ((lane >> 4) << 3);
                uint32_t bb = sw128((uint32_t)(nrow*128 + kk*32 + ((lane >> 3) & 1)*16));
                uint32_t r0,r1,r2,r3;
                LDSM_X4(r0,r1,r2,r3, sb + TILE16 + bb);
                bfrag[2*g][0]=r0; bfrag[2*g][1]=r1; bfrag[2*g+1][0]=r2; bfrag[2*g+1][1]=r3;
            }
#pragma unroll
            for (int f=0; f<2; f++)
#pragma unroll
                for (int j=0; j<8; j++)
                    MMAF16(acc[f][j], af[f], bfrag[j]);
        }
    }

#pragma unroll
    for (int f=0; f<2; f++){
        int r = m0 + wm*32 + f*16 + (lane >> 2);
#pragma unroll
        for (int j=0; j<8; j++){
            int cc = n0 + wn*64 + j*8 + (lane & 3)*2;
            *(float2*)&C[(size_t)r*Dm + cc]     = make_float2(acc[f][j][0], acc[f][j][1]);
            *(float2*)&C[(size_t)(r+8)*Dm + cc] = make_float2(acc[f][j][2], acc[f][j][3]);
        }
    }
}

// ================= X -> fp16 =================
__global__ void tohalf_kernel(const float* __restrict__ src, __half* __restrict__ dst)
{
    int i = blockIdx.x * blockDim.x + threadIdx.x;
    float4 v = ((const float4*)src)[i];
    uint2 o;
    o.x = f2h2(v.x, v.y);
    o.y = f2h2(v.z, v.w);
    ((uint2*)dst)[i] = o;
}

// 4 matrices W [K][N] -> Wt [N][K] fp16, z selects
__global__ void wsplit_kernel(const float* __restrict__ W0, const float* __restrict__ W1,
                              const float* __restrict__ W2, const float* __restrict__ W3,
                              __half* __restrict__ thBase)
{
    __shared__ float tile[32][33];
    int z = blockIdx.z;
    const float* W = (z==0)?W0:((z==1)?W1:((z==2)?W2:W3));
    __half* th = thBase + (size_t)z*Dm*Dm;
    int n0 = blockIdx.x * 32, k0 = blockIdx.y * 32;
    int tx = threadIdx.x, ty = threadIdx.y;
    for (int r = ty; r < 32; r += 8) tile[r][tx] = W[(size_t)(k0 + r) * Dm + n0 + tx];
    __syncthreads();
    for (int r = ty; r < 32; r += 8)
        th[(size_t)(n0 + r) * Dm + k0 + tx] = __float2half(tile[tx][r]);
}

// ---------------- small projections ----------------
__global__ __launch_bounds__(256) void proj_small_kernel(const float* __restrict__ X,
                                                         const float* __restrict__ Wb_,
                                                         const float* __restrict__ Wd_,
                                                         const float* __restrict__ Wm_)
{
    __shared__ float4 wb[256], wd[256], wm[256];
    int tid = threadIdx.x, lane = tid & 31, wid = tid >> 5;
    int t = blockIdx.x * 8 + wid;
    float acc[12];
#pragma unroll
    for (int i=0;i<12;i++) acc[i]=0.0f;
    for (int e0 = 0; e0 < 1024; e0 += 256){
        __syncthreads();
        wb[tid] = ((const float4*)Wb_)[e0 + tid];
        wd[tid] = ((const float4*)Wd_)[e0 + tid];
        wm[tid] = ((const float4*)Wm_)[e0 + tid];
        __syncthreads();
        for (int e = lane; e < 256; e += 32){
            float xv = X[(size_t)t*Dm + e0 + e];
            float4 b = wb[e], d = wd[e], m = wm[e];
            acc[0]+=xv*b.x; acc[1]+=xv*b.y; acc[2]+=xv*b.z; acc[3]+=xv*b.w;
            acc[4]+=xv*d.x; acc[5]+=xv*d.y; acc[6]+=xv*d.z; acc[7]+=xv*d.w;
            acc[8]+=xv*m.x; acc[9]+=xv*m.y; acc[10]+=xv*m.z; acc[11]+=xv*m.w;
        }
    }
#pragma unroll
    for (int i=0;i<12;i++){
        float s = acc[i];
        for (int o=16;o;o>>=1) s += __shfl_xor_sync(0xffffffffu, s, o);
        acc[i] = s;
    }
    if (lane == 0){
#pragma unroll
        for (int c=0;c<4;c++){
            g_beta [t*Hh+c] = sigm(acc[c]);
            g_gamma[t*Hh+c] = sigm(acc[4+c]);
            g_mixlin[t*Hh+c] = acc[8+c];
        }
    }
}

// ---------------- register-blocked depthwise causal conv + silu (q,k,v) --------
#define CONV_T 8
__global__ __launch_bounds__(256) void conv_silu3_kernel(
    const float* __restrict__ l0, const float* __restrict__ l1, const float* __restrict__ l2,
    const float* __restrict__ c0, const float* __restrict__ c1, const float* __restrict__ c2,
    float* __restrict__ o0, float* __restrict__ o1, float* __restrict__ o2)
{
    int which = blockIdx.y;
    const float* lin = (which==0)?l0:((which==1)?l1:l2);
    const float* cw  = (which==0)?c0:((which==1)?c1:c2);
    float* out       = (which==0)?o0:((which==1)?o1:o2);
    int dsilu = (which < 2);

    int t0 = blockIdx.x * CONV_T;
    int c  = threadIdx.x * 4;
    const int strd = Dm / 4;
    const float4* L = (const float4*)lin + (size_t)t0 * strd + (c >> 2);
    float4* O       = (float4*)out + (size_t)t0 * strd + (c >> 2);

    float4 wv0 = ((const float4*)cw)[c+0];
    float4 wv1 = ((const float4*)cw)[c+1];
    float4 wv2 = ((const float4*)cw)[c+2];
    float4 wv3 = ((const float4*)cw)[c+3];

    float4 h1, h2, h3;
    if ((t0 % Lseq) == 0){
        h1 = h2 = h3 = make_float4(0,0,0,0);
    } else {
        h1 = L[-1*strd]; h2 = L[-2*strd]; h3 = L[-3*strd];
    }

#pragma unroll
    for (int i=0; i<CONV_T; i++){
        float4 x = L[i*strd];
        float4 a;
        a.x = x.x*wv0.w + h1.x*wv0.z + h2.x*wv0.y + h3.x*wv0.x;
        a.y = x.y*wv1.w + h1.y*wv1.z + h2.y*wv1.y + h3.y*wv1.x;
        a.z = x.z*wv2.w + h1.z*wv2.z + h2.z*wv2.y + h3.z*wv2.x;
        a.w = x.w*wv3.w + h1.w*wv3.z + h2.w*wv3.y + h3.w*wv3.x;
        h3 = h2; h2 = h1; h1 = x;
        float4 y;
        y.x = a.x * sigm(a.x); y.y = a.y * sigm(a.y);
        y.z = a.z * sigm(a.z); y.w = a.w * sigm(a.w);
        if (dsilu){
            y.x = y.x * sigm(y.x); y.y = y.y * sigm(y.y);
            y.z = y.z * sigm(y.z); y.w = y.w * sigm(y.w);
        }
        O[i*strd] = y;
    }
}

__global__ void conv_mix_kernel(const float* __restrict__ cm, const float* __restrict__ mbias)
{
    int e = blockIdx.x*blockDim.x + threadIdx.x;
    if (e >= Mrows*Hh) return;
    int t = e / Hh, h = e % Hh;
    int tl = t % Lseq;
    float w0=cm[h*4+0], w1=cm[h*4+1], w2=cm[h*4+2], w3=cm[h*4+3];
    float acc = g_mixlin[e]*w3;
    if (tl>=1) acc += g_mixlin[e-Hh]*w2;
    if (tl>=2) acc += g_mixlin[e-2*Hh]*w1;
    if (tl>=3) acc += g_mixlin[e-3*Hh]*w0;
    float y = acc * sigm(acc);
    g_mix[e] = sigm(y + mbias[h]);
}

// ---------------- per-chunk precompute + EMA local scan ----------------
#define SQS 260
__global__ __launch_bounds__(256) void chunk_pre_kernel()
{
    extern __shared__ float sm4[];
    float* sq  = sm4;
    float* skk = sq  + 32*SQS;
    float* sv  = skk + 32*SQS;
    float* sT  = sv  + 32*SQS;
    float* sb  = sT  + 1024;
    float* sg  = sb  + 32;
    int z = blockIdx.x;
    int b  = z >> 8;
    int h  = (z >> 6) & 3;
    int nc = z & 63;
    int t0 = b*Lseq + nc*CHK;
    int cb = h*DHd;
    int tid = threadIdx.x, lane = tid & 31, wid = tid >> 5;

    for (int e=tid; e<32*64; e+=256){
        int r=e>>6, c=(e&63)*4;
        *(float4*)&sq [r*SQS+c] = *(const float4*)&g_q[(size_t)(t0+r)*Dm + cb + c];
        *(float4*)&skk[r*SQS+c] = *(const float4*)&g_k[(size_t)(t0+r)*Dm + cb + c];
        *(float4*)&sv [r*SQS+c] = *(const float4*)&g_v[(size_t)(t0+r)*Dm + cb + c];
    }
    if (tid < 32){
        sb[tid] = g_beta[(t0+tid)*Hh + h];
        sg[tid] = g_gamma[(t0+tid)*Hh + h];
    }
    __syncthreads();

    for (int r=wid; r<32; r+=8){
        float s=0.0f;
        for (int c=lane;c<256;c+=32){ float v=sq[r*SQS+c]; s+=v*v; }
        for (int o=16;o;o>>=1) s += __shfl_xor_sync(0xffffffffu,s,o);
        float rn = rsqrtf(s + 1e-6f);
        for (int c=lane;c<256;c+=32){ sq[r*SQS+c] *= rn; }
        s=0.0f;
        for (int c=lane;c<256;c+=32){ float v=skk[r*SQS+c]; s+=v*v; }
        for (int o=16;o;o>>=1) s += __shfl_xor_sync(0xffffffffu,s,o);
        rn = rsqrtf(s + 1e-6f);
        for (int c=lane;c<256;c+=32){ skk[r*SQS+c] *= rn; }
    }
    __syncthreads();

    {
        int ti = tid >> 4, tj = tid & 15;
        int i0 = 2*ti, j0 = 2*tj;
        float a00=0,a01=0,a10=0,a11=0;
        float q00=0,q01=0,q10=0,q11=0;
#pragma unroll 8
        for (int p=0;p<256;p+=4){
            float4 ki0 = *(float4*)&skk[i0*SQS+p];
            float4 ki1 = *(float4*)&skk[(i0+1)*SQS+p];
            float4 qi0 = *(float4*)&sq [i0*SQS+p];
            float4 qi1 = *(float4*)&sq [(i0+1)*SQS+p];
            float4 kj0 = *(float4*)&skk[j0*SQS+p];
            float4 kj1 = *(float4*)&skk[(j0+1)*SQS+p];
            a00 += ki0.x*kj0.x + ki0.y*kj0.y + ki0.z*kj0.z + ki0.w*kj0.w;
            a01 += ki0.x*kj1.x + ki0.y*kj1.y + ki0.z*kj1.z + ki0.w*kj1.w;
            a10 += ki1.x*kj0.x + ki1.y*kj0.y + ki1.z*kj0.z + ki1.w*kj0.w;
            a11 += ki1.x*kj1.x + ki1.y*kj1.y + ki1.z*kj1.z + ki1.w*kj1.w;
            q00 += qi0.x*kj0.x + qi0.y*kj0.y + qi0.z*kj0.z + qi0.w*kj0.w;
            q01 += qi0.x*kj1.x + qi0.y*kj1.y + qi0.z*kj1.z + qi0.w*kj1.w;
            q10 += qi1.x*kj0.x + qi1.y*kj0.y + qi1.z*kj0.z + qi1.w*kj0.w;
            q11 += qi1.x*kj1.x + qi1.y*kj1.y + qi1.z*kj1.z + qi1.w*kj1.w;
        }
        sT[i0*32+j0]       = (j0   < i0  ) ? -sb[i0]*a00   : 0.0f;
        sT[i0*32+j0+1]     = (j0+1 < i0  ) ? -sb[i0]*a01   : 0.0f;
        sT[(i0+1)*32+j0]   = (j0   < i0+1) ? -sb[i0+1]*a10 : 0.0f;
        sT[(i0+1)*32+j0+1] = (j0+1 < i0+1) ? -sb[i0+1]*a11 : 0.0f;
        size_t abase = (size_t)z*1024;
        g_A2[abase + i0*32+j0]       = (j0   <= i0  ) ? q00 : 0.0f;
        g_A2[abase + i0*32+j0+1]     = (j0+1 <= i0  ) ? q01 : 0.0f;
        g_A2[abase + (i0+1)*32+j0]   = (j0   <= i0+1) ? q10 : 0.0f;
        g_A2[abase + (i0+1)*32+j0+1] = (j0+1 <= i0+1) ? q11 : 0.0f;
    }
    __syncthreads();

    // fwd-subst on warp 0; warps 1-7 write k^T fp16 concurrently
    size_t ktb = (size_t)z*8192;
    if (wid == 0){
        for (int i=1;i<32;i++){
            float a = sT[i*32+lane];
            float acc = 0.0f;
            for (int j=1;j<32;j++){
                float aij = __shfl_sync(0xffffffffu, a, j);
                acc += aij * sT[j*32+lane];
            }
            if (lane < i) sT[i*32+lane] = a + acc;
            __syncwarp();
        }
        sT[lane*32+lane] += 1.0f;
    } else {
        for (int e=tid-32; e<8192; e+=224){
            int r=e>>5, j=e&31;
            g_kt16[ktb + r*32 + j] = __float2half(skk[j*SQS + r]);
        }
    }
    __syncthreads();

    for (int e=tid; e<1024; e+=256) sT[e] *= sb[e&31];
    __syncthreads();

    size_t wqb = (size_t)z*16384;
    {
        int ri = tid >> 6;
        int tc = (tid & 63) * 4;
        float4 ua[8], wa[8];
#pragma unroll
        for (int r=0;r<8;r++){ ua[r]=make_float4(0,0,0,0); wa[r]=make_float4(0,0,0,0); }
        for (int j=0;j<32;j++){
            float4 v4 = *(float4*)&sv [j*SQS + tc];
            float4 k4 = *(float4*)&skk[j*SQS + tc];
#pragma unroll
            for (int r=0;r<8;r++){
                float tb = sT[(ri*8+r)*32 + j];
                ua[r].x += tb*v4.x; ua[r].y += tb*v4.y; ua[r].z += tb*v4.z; ua[r].w += tb*v4.w;
                wa[r].x += tb*k4.x; wa[r].y += tb*k4.y; wa[r].z += tb*k4.z; wa[r].w += tb*k4.w;
            }
        }
#pragma unroll
        for (int r=0;r<8;r++){
            int i = ri*8 + r;
            *(float4*)&g_u[(size_t)(t0+i)*Dm + cb + tc] = ua[r];
            *(uint2*)&g_wq16[wqb + i*256 + tc] = make_uint2(f2h2(wa[r].x, wa[r].y), f2h2(wa[r].z, wa[r].w));
            float4 q4 = *(float4*)&sq[i*SQS + tc];
            *(uint2*)&g_wq16[wqb + (32+i)*256 + tc] = make_uint2(f2h2(q4.x, q4.y), f2h2(q4.z, q4.w));
        }
    }

    {
        int c = tid;
        float s = 0.0f, pg = 1.0f;
#pragma unroll
        for (int t=0;t<CHK;t++){
            float g = sg[t];
            s = g*s + (1.0f-g)*sv[t*SQS + c];
            pg *= g;
            g_ema[(size_t)(t0+t)*Dm + cb + c] = s;
            if (c == 0) g_pg[(t0+t)*Hh + h] = pg;
        }
    }
}

// ---------------- fp16 MMA recurrence, dv-sliced, double-buffered ----------------
__global__ __launch_bounds__(256) void recurrence_kernel()
{
    extern __shared__ char sm5[];
    uint32_t raw = smem_u32(sm5);
    uint32_t base = (raw + 127u) & ~127u;
    char* p0 = sm5 + (base - raw);

    const uint32_t oWQ0=0, oWQ1=32768;
    const uint32_t oKT0=65536, oKT1=86016;
    const uint32_t oSh=106496, oSl=126976;
    const uint32_t oUA=147456;
    const uint32_t oU0=150016, oU1=154624;
    const uint32_t oA20=159232, oA21=163840;
    const uint32_t oRq=168448, oUA32=173056;

    float* Rq_s = (float*)(p0 + oRq);
    float* ua_s = (float*)(p0 + oUA32);
    char* pSh = p0 + oSh; char* pSl = p0 + oSl;
    char* pUA = p0 + oUA;
    uint32_t uSh = base+oSh, uSl = base+oSl, uUA = base+oUA;

    int bx = blockIdx.x;
    int bh = bx >> 3, vb = bx & 7;
    int b = bh >> 2, h = (bx >> 3) & 3;
    int cvb = h*DHd + vb*32;
    int tid = threadIdx.x, lane = tid & 31, wid = tid >> 5;
    int rm = wid >> 1, rn = wid & 1;

    float accS[2][4][4];
#pragma unroll
    for (int tm=0;tm<2;tm++)
#pragma unroll
        for (int tn=0;tn<4;tn++)
#pragma unroll
            for (int e=0;e<4;e++) accS[tm][tn][e]=0.0f;

    auto load_chunk = [&](int cc, int sl){
        int slot = bh*NCk + cc;
        int tt0 = b*Lseq + cc*CHK;
        const __half* gwq = g_wq16 + (size_t)slot*16384;
        const __half* gkt = g_kt16 + (size_t)slot*8192;
        uint32_t uWQ = base + (sl ? oWQ1 : oWQ0);
        uint32_t uKT = base + (sl ? oKT1 : oKT0);
        uint32_t uU  = base + (sl ? oU1  : oU0);
        uint32_t uA2 = base + (sl ? oA21 : oA20);
#pragma unroll
        for (int t=0;t<8;t++){
            int c = tid + t*256;
            int row = c >> 5, col = c & 31;
            cpa16(uWQ + row*512 + ((uint32_t)(col ^ (row & 7)) << 4), gwq + c*8);
        }
#pragma unroll
        for (int t=0;t<4;t++){
            int c = tid + t*256;
            int row = c >> 2, col = c & 3;
            cpa16(uKT + row*80 + (col << 4), gkt + c*8);
        }
        {
            int row = tid >> 3, col = tid & 7;
            cpa16(uU + row*144 + col*16, &g_u[(size_t)(tt0+row)*Dm + cvb + col*4]);
            cpa16(uA2 + row*144 + col*16, g_A2 + (size_t)slot*1024 + tid*4);
        }
        CP_COMMIT();
    };

    load_chunk(0, 0);

    for (int ci=0; ci<NCk; ci++){
        __syncthreads();
        int sl = ci & 1;
        int t0 = b*Lseq + ci*CHK;
        uint32_t uWQ = base + (sl ? oWQ1 : oWQ0);
        uint32_t uKT = base + (sl ? oKT1 : oKT0);
        float* u_s  = (float*)(p0 + (sl ? oU1  : oU0));
        float* A2_s = (float*)(p0 + (sl ? oA21 : oA20));

        if (ci+1 < NCk) load_chunk(ci+1, (ci+1)&1);

#pragma unroll
        for (int tm=0;tm<2;tm++)
#pragma unroll
        for (int tn=0;tn<4;tn++){
            int r = wid*32 + tm*16 + (lane>>2);
            int c = tn*8 + (lane&3)*2;
            uint32_t hw, lw;
            split2h(accS[tm][tn][0], accS[tm][tn][1], hw, lw);
            *(uint32_t*)(pSh + r*80 + c*2) = hw;
            *(uint32_t*)(pSl + r*80 + c*2) = lw;
            split2h(accS[tm][tn][2], accS[tm][tn][3], hw, lw);
            *(uint32_t*)(pSh + (r+8)*80 + c*2) = hw;
            *(uint32_t*)(pSl + (r+8)*80 + c*2) = lw;
        }

        if (ci == NCk-1) { CP_WAIT(0); } else { CP_WAIT(1); }
        __syncthreads();

        float accR[2][4];
#pragma unroll
        for (int j=0;j<2;j++)
#pragma unroll
            for (int e=0;e<4;e++) accR[j][e]=0.0f;

#pragma unroll 4
        for (int kk=0; kk<16; kk++){
            int arow = rm*16 + (lane & 7) + ((lane >> 3) & 1)*8;
            int achunk = kk*2 + (lane >> 4);
            uint32_t af[4];
            LDSM_X4(af[0],af[1],af[2],af[3], uWQ + arow*512 + ((uint32_t)(achunk ^ (arow & 7)) << 4));

            int krow = kk*16 + (lane & 7) + ((lane >> 3) & 1)*8;
            uint32_t boff = krow*80 + rn*32 + ((lane >> 4) << 4);
            uint32_t s0,s1,s2,s3;
            LDSM_X4T(s0,s1,s2,s3, uSh + boff);
            uint32_t bh0[2] = {s0,s1}, bh1[2] = {s2,s3};
            LDSM_X4T(s0,s1,s2,s3, uSl + boff);
            uint32_t bl0[2] = {s0,s1}, bl1[2] = {s2,s3};

            MMAF16(accR[0], af, bh0);
            MMAF16(accR[0], af, bl0);
            MMAF16(accR[1], af, bh1);
            MMAF16(accR[1], af, bl1);
        }

        if (wid < 4){
#pragma unroll
            for (int j=0;j<2;j++){
                int c = rn*16 + j*8 + (lane&3)*2;
                int r1 = rm*16 + (lane>>2);
                float ua0 = u_s[r1*36+c]   - accR[j][0];
                float ua1 = u_s[r1*36+c+1] - accR[j][1];
                *(uint32_t*)(pUA + r1*80 + c*2) = f2h2(ua0, ua1);
                *(float2*)&ua_s[r1*36+c] = make_float2(ua0, ua1);
                float ua2 = u_s[(r1+8)*36+c]   - accR[j][2];
                float ua3 = u_s[(r1+8)*36+c+1] - accR[j][3];
                *(uint32_t*)(pUA + (r1+8)*80 + c*2) = f2h2(ua2, ua3);
                *(float2*)&ua_s[(r1+8)*36+c] = make_float2(ua2, ua3);
            }
        } else {
#pragma unroll
            for (int j=0;j<2;j++){
                int c = rn*16 + j*8 + (lane&3)*2;
                int r1 = (rm-2)*16 + (lane>>2);
                *(float2*)&Rq_s[r1*36+c]     = make_float2(accR[j][0], accR[j][1]);
                *(float2*)&Rq_s[(r1+8)*36+c] = make_float2(accR[j][2], accR[j][3]);
            }
        }
        __syncthreads();

        {
            int c = tid & 31, rb = tid >> 5;
            float o0 = Rq_s[rb*36+c], o1 = Rq_s[(rb+8)*36+c];
            float o2 = Rq_s[(rb+16)*36+c], o3 = Rq_s[(rb+24)*36+c];
#pragma unroll 8
            for (int j=0;j<32;j++){
                float uv = ua_s[j*36+c];
                o0 += A2_s[rb*36+j]*uv;
                o1 += A2_s[(rb+8)*36+j]*uv;
                o2 += A2_s[(rb+16)*36+j]*uv;
                o3 += A2_s[(rb+24)*36+j]*uv;
            }
            g_od[(size_t)(t0+rb)*Dm + cvb + c]      = o0;
            g_od[(size_t)(t0+rb+8)*Dm + cvb + c]    = o1;
            g_od[(size_t)(t0+rb+16)*Dm + cvb + c]   = o2;
            g_od[(size_t)(t0+rb+24)*Dm + cvb + c]   = o3;
        }

#pragma unroll
        for (int kk=0; kk<2; kk++){
            uint32_t a_f[2][4];
#pragma unroll
            for (int tm=0;tm<2;tm++){
                int mrow = wid*32 + tm*16 + (lane & 7) + ((lane >> 3) & 1)*8;
                LDSM_X4(a_f[tm][0],a_f[tm][1],a_f[tm][2],a_f[tm][3],
                        uKT + mrow*80 + kk*32 + ((lane >> 4) << 4));
            }
            uint32_t bu[4][2];
#pragma unroll
            for (int g=0; g<2; g++){
                int krow = kk*16 + (lane & 7) + ((lane >> 3) & 1)*8;
                uint32_t r0,r1,r2,r3;
                LDSM_X4T(r0,r1,r2,r3, uUA + krow*80 + g*32 + ((lane >> 4) << 4));
                bu[2*g][0]=r0; bu[2*g][1]=r1; bu[2*g+1][0]=r2; bu[2*g+1][1]=r3;
            }
#pragma unroll
            for (int tm=0;tm<2;tm++)
#pragma unroll
                for (int tn=0;tn<4;tn++)
                    MMAF16(accS[tm][tn], a_f[tm], bu[tn]);
        }
    }
}

// ---------------- EMA cross-chunk scan ------------
__global__ void ema_seq_kernel()
{
    extern __shared__ float sE[];
    float* sP = sE + NCk*DHd;
    int bh = blockIdx.x;
    int b = bh >> 2, h = bh & 3;
    int cb = h*DHd;
    int tid = threadIdx.x;

    for (int i = tid; i < NCk*DHd; i += 256){
        int j = i >> 8, col = i & 255;
        sE[i] = g_ema[(size_t)(b*Lseq + j*CHK + CHK-1)*Dm + cb + col];
    }
    if (tid < NCk) sP[tid] = g_pg[(b*Lseq + tid*CHK + CHK-1)*Hh + h];
    __syncthreads();

    int c = tid;
    float S = 0.0f;
    for (int j=0;j<NCk;j++){
        g_sst[(size_t)(bh*NCk + j)*DHd + c] = S;
        S = sE[j*DHd + c] + sP[j]*S;
    }
}

// ---------------- mix + rmsnorm -> fp16 output ----------------
__global__ __launch_bounds__(256) void combine_kernel(const float* __restrict__ rmsw)
{
    int t = blockIdx.x, c = threadIdx.x;
    int lane = c & 31, w = c >> 5;
    int b = t / Lseq, tl = t % Lseq, chunk = tl >> 5;
    __shared__ float red[4][8];
    float o[4];
#pragma unroll
    for (int h=0;h<Hh;h++){
        float mix = g_mix[t*Hh+h];
        size_t idx = (size_t)t*Dm + h*DHd + c;
        float ema = g_ema[idx] + g_pg[t*Hh+h] * g_sst[(size_t)((b*4+h)*NCk + chunk)*DHd + c];
        o[h] = (1.0f-mix)*g_od[idx] + mix*ema;
        float s = o[h]*o[h];
        for (int off=16;off;off>>=1) s += __shfl_xor_sync(0xffffffffu,s,off);
        if (lane==0) red[h][w]=s;
    }
    __syncthreads();
#pragma unroll
    for (int h=0;h<Hh;h++){
        float tot = red[h][0]+red[h][1]+red[h][2]+red[h][3]+red[h][4]+red[h][5]+red[h][6]+red[h][7];
        float scale = rsqrtf(tot*(1.0f/256.0f) + 1e-5f);
        g_oc16[(size_t)t*Dm + h*DHd + c] = __float2half(o[h]*scale*rmsw[c]);
    }
}

// ---------------- launcher ----------------
extern "C" void kernel_launch(void* const* d_in, const int* in_sizes, int n_in,
                              void* d_out, int out_size)
{
    const float* X    = (const float*)d_in[0];
    const float* Wq   = (const float*)d_in[1];
    const float* Wk   = (const float*)d_in[2];
    const float* Wv   = (const float*)d_in[3];
    const float* cq   = (const float*)d_in[4];
    const float* ck   = (const float*)d_in[5];
    const float* cv   = (const float*)d_in[6];
    const float* Wb   = (const float*)d_in[7];
    const float* Wdec = (const float*)d_in[8];
    const float* Wmix = (const float*)d_in[9];
    const float* cmix = (const float*)d_in[10];
    const float* mbias= (const float*)d_in[11];
    const float* rmsw = (const float*)d_in[12];
    const float* Wo   = (const float*)d_in[13];
    float* out = (float*)d_out;
    (void)in_sizes; (void)n_in; (void)out_size;

    float *p_qlin,*p_klin,*p_vlin,*p_q,*p_k,*p_v;
    __half *p_x16,*p_oc16,*p_wt16;
    cudaGetSymbolAddress((void**)&p_qlin, g_qlin);
    cudaGetSymbolAddress((void**)&p_klin, g_klin);
    cudaGetSymbolAddress((void**)&p_vlin, g_vlin);
    cudaGetSymbolAddress((void**)&p_x16,  g_x16);
    cudaGetSymbolAddress((void**)&p_oc16, g_oc16);
    cudaGetSymbolAddress((void**)&p_wt16, g_wt16);
    cudaGetSymbolAddress((void**)&p_q, g_q);
    cudaGetSymbolAddress((void**)&p_k, g_k);
    cudaGetSymbolAddress((void**)&p_v, g_v);

    static cudaStream_t s2 = nullptr;
    static cudaEvent_t evFork = nullptr, evW = nullptr, evProj = nullptr, evPre = nullptr, evEma = nullptr;
    if (!s2){
        cudaStreamCreateWithFlags(&s2, cudaStreamNonBlocking);
        cudaEventCreateWithFlags(&evFork, cudaEventDisableTiming);
        cudaEventCreateWithFlags(&evW,    cudaEventDisableTiming);
        cudaEventCreateWithFlags(&evProj, cudaEventDisableTiming);
        cudaEventCreateWithFlags(&evPre,  cudaEventDisableTiming);
        cudaEventCreateWithFlags(&evEma,  cudaEventDisableTiming);
    }

    const int SMEMG = 3*STAGEF + 256;
    cudaFuncSetAttribute(mma_gemm_kernel, cudaFuncAttributeMaxDynamicSharedMemorySize, SMEMG);

    // side stream: wsplit (needed by GEMM), then proj_small + conv_mix
    cudaEventRecord(evFork, 0);
    cudaStreamWaitEvent(s2, evFork, 0);
    dim3 wg(32,32,4), wb2(32,8);
    wsplit_kernel<<<wg,wb2,0,s2>>>(Wq, Wk, Wv, Wo, p_wt16);
    cudaEventRecord(evW, s2);
    proj_small_kernel<<<Mrows/8,256,0,s2>>>(X, Wb, Wdec, Wmix);
    conv_mix_kernel<<<(Mrows*Hh+255)/256,256,0,s2>>>(cmix, mbias);
    cudaEventRecord(evProj, s2);

    // main chain
    tohalf_kernel<<<MD/4/256,256>>>(X, p_x16);
    cudaStreamWaitEvent(0, evW, 0);

    dim3 gg3(Dm/128, Mrows/128, 3);
    mma_gemm_kernel<<<gg3,256,SMEMG>>>(p_x16, p_wt16, 0, p_qlin, p_klin, p_vlin);

    dim3 cg(Mrows/CONV_T, 3);
    conv_silu3_kernel<<<cg,256>>>(p_qlin, p_klin, p_vlin, cq, ck, cv, p_q, p_k, p_v);

    // chunk_pre needs beta/gamma from the side stream
    cudaStreamWaitEvent(0, evProj, 0);

    const int SMEM4 = (3*32*SQS + 1024 + 64) * 4;
    cudaFuncSetAttribute(chunk_pre_kernel, cudaFuncAttributeMaxDynamicSharedMemorySize, SMEM4);
    chunk_pre_kernel<<<Bb*Hh*NCk, 256, SMEM4>>>();
    cudaEventRecord(evPre, 0);

    cudaStreamWaitEvent(s2, evPre, 0);
    const int SMEME = (NCk*DHd + NCk) * 4;
    cudaFuncSetAttribute(ema_seq_kernel, cudaFuncAttributeMaxDynamicSharedMemorySize, SMEME);
    ema_seq_kernel<<<Bb*Hh, 256, SMEME, s2>>>();
    cudaEventRecord(evEma, s2);

    const int SMEM5 = 177664 + 256;
    cudaFuncSetAttribute(recurrence_kernel, cudaFuncAttributeMaxDynamicSharedMemorySize, SMEM5);
    recurrence_kernel<<<Bb*Hh*8, 256, SMEM5>>>();

    cudaStreamWaitEvent(0, evEma, 0);
    combine_kernel<<<Mrows,256>>>(rmsw);

    dim3 gg1(Dm/128, Mrows/128, 1);
    mma_gemm_kernel<<<gg1,256,SMEMG>>>(p_oc16, p_wt16, 3, out, out, out);
}